// round 1
// baseline (speedup 1.0000x reference)
#include <cuda_runtime.h>
#include <math.h>

namespace {
constexpr int NDIM   = 4;
constexpr int KW     = 32;      // N_WIDTH
constexpr int NN     = 193;     // N_NODES
constexpr int TILE_I = 224;
constexpr int THREADS = 1024;
constexpr int IPW    = TILE_I / 32;           // samples per warp = 7

constexpr int WIN_ELEMS  = KW * NN * NDIM;    // 24704
constexpr int WOUT_ELEMS = KW * NN;           // 6176

// shared layout (float words)
constexpr int OFF_WIN   = 0;                               // [(node*4+j)*32 + k]
constexpr int OFF_WOUT  = OFF_WIN + WIN_ELEMS;             // [node*32 + k]
constexpr int OFF_PHI   = OFF_WOUT + WOUT_ELEMS;           // float4 [TILE_I*4]
constexpr int OFF_DPHI  = OFF_PHI  + TILE_I * 4 * 4;
constexpr int OFF_DDPHI = OFF_DPHI + TILE_I * 4 * 4;
constexpr int OFF_NODE  = OFF_DDPHI + TILE_I * 4 * 4;      // int [TILE_I*4]
constexpr int SMEM_FLOATS = OFF_NODE + TILE_I * 4;
constexpr int SMEM_BYTES  = SMEM_FLOATS * 4;               // 170112 B
}

__global__ __launch_bounds__(THREADS, 1)
void kann_kernel(const float* __restrict__ x,
                 const float* __restrict__ Win,
                 const float* __restrict__ Wout,
                 float* __restrict__ out,
                 int I)
{
    extern __shared__ float sm[];
    float*  sWin   = sm + OFF_WIN;
    float*  sWout  = sm + OFF_WOUT;
    float4* sPhi   = (float4*)(sm + OFF_PHI);
    float4* sDphi  = (float4*)(sm + OFF_DPHI);
    float4* sDdphi = (float4*)(sm + OFF_DDPHI);
    int*    sNode  = (int*)(sm + OFF_NODE);

    const int tid    = threadIdx.x;
    const int i_base = blockIdx.x * TILE_I;

    // ---- stage weights into SMEM, transposed so lane==k is contiguous ----
    for (int e = tid; e < WIN_ELEMS; e += THREADS) {
        int k = e / (NN * NDIM);
        int r = e - k * (NN * NDIM);         // node*4 + j
        sWin[r * KW + k] = Win[e];
    }
    for (int e = tid; e < WOUT_ELEMS; e += THREADS) {
        int k    = e / NN;
        int node = e - k * NN;
        sWout[node * KW + k] = Wout[e];
    }

    const float c0 = -0.5625f, c1 = 1.6875f, c2 = -1.6875f, c3 = 0.5625f;
    const float TH = 1.0f / 3.0f;

    // ---- phase 1: per-(sample,dim) basis values + derivatives ----
    if (tid < TILE_I * NDIM) {
        const int li = tid >> 2;
        const int j  = tid & 3;
        const int i  = i_base + li;
        if (i < I) {
            float xv = x[i * NDIM + j];
            // layer_transform on [-1,1], 193 nodes, 64 elements
            float xs = 192.0f * (xv + 1.0f) / 2.0f;
            float fe = floorf(xs / 3.0f);
            fe = fminf(fmaxf(fe, 0.0f), 63.0f);
            float nl = 3.0f * fe;
            float xr = 2.0f * (xs - nl) / 3.0f - 1.0f;

            float d0 = xr + 1.0f, d1 = xr + TH, d2 = xr - TH, d3 = xr - 1.0f;
            float d01 = d0 * d1, d23 = d2 * d3;
            float d02 = d0 * d2, d03 = d0 * d3, d12 = d1 * d2, d13 = d1 * d3;

            float4 ph, dp, dd;
            ph.x = c0 * (d1 * d23);
            ph.y = c1 * (d0 * d23);
            ph.z = c2 * (d01 * d3);
            ph.w = c3 * (d01 * d2);
            dp.x = c0 * (d23 + d13 + d12);
            dp.y = c1 * (d23 + d03 + d02);
            dp.z = c2 * (d13 + d03 + d01);
            dp.w = c3 * (d12 + d02 + d01);
            float s = d0 + d1 + d2 + d3;
            dd.x = 2.0f * c0 * (s - d0);
            dd.y = 2.0f * c1 * (s - d1);
            dd.z = 2.0f * c2 * (s - d2);
            dd.w = 2.0f * c3 * (s - d3);

            sPhi[tid]   = ph;
            sDphi[tid]  = dp;
            sDdphi[tid] = dd;
            sNode[tid]  = 3 * (int)fe;
        }
    }
    __syncthreads();

    // ---- phase 2: warp = one sample, lane = width k ----
    const int warp = tid >> 5;
    const int lane = tid & 31;
    const int IK   = I * KW;

    #pragma unroll
    for (int s = 0; s < IPW; s++) {
        int li = warp * IPW + s;
        int i  = i_base + li;
        if (i >= I) break;

        float tv = 0.f, dtv = 0.f, ddtv = 0.f;
        #pragma unroll
        for (int j = 0; j < 4; j++) {
            int idx  = li * 4 + j;
            int node = sNode[idx];
            float4 ph = sPhi[idx];
            float4 dp = sDphi[idx];
            float4 dd = sDdphi[idx];
            const float* wb = sWin + (node * 4 + j) * KW + lane;
            float w0 = wb[0 * 4 * KW];
            float w1 = wb[1 * 4 * KW];
            float w2 = wb[2 * 4 * KW];
            float w3 = wb[3 * 4 * KW];
            tv   += w0 * ph.x + w1 * ph.y + w2 * ph.z + w3 * ph.w;
            dtv  += w0 * dp.x + w1 * dp.y + w2 * dp.z + w3 * dp.w;
            ddtv += w0 * dd.x + w1 * dd.y + w2 * dd.z + w3 * dd.w;
        }
        dtv  *= 64.0f;    // 1/delta,   delta = 1/64 exactly
        ddtv *= 4096.0f;  // 1/delta^2

        // outer layer on t, domain [-3,3]
        float xs = 192.0f * (tv + 3.0f) / 6.0f;
        float fe = floorf(xs / 3.0f);
        fe = fminf(fmaxf(fe, 0.0f), 63.0f);
        float nl = 3.0f * fe;
        float xr = 2.0f * (xs - nl) / 3.0f - 1.0f;

        float e0 = xr + 1.0f, e1 = xr + TH, e2 = xr - TH, e3 = xr - 1.0f;
        float e01 = e0 * e1, e23 = e2 * e3;
        float p0 = c0 * (e1 * e23);
        float p1 = c1 * (e0 * e23);
        float p2 = c2 * (e01 * e3);
        float p3 = c3 * (e01 * e2);

        const float* wo = sWout + (3 * (int)fe) * KW + lane;
        float y = p0 * wo[0] + p1 * wo[KW] + p2 * wo[2 * KW] + p3 * wo[3 * KW];

        int o = i * KW + lane;
        out[o]          = y;
        out[o + IK]     = tv;
        out[o + 2 * IK] = dtv;
        out[o + 3 * IK] = ddtv;
    }
}

extern "C" void kernel_launch(void* const* d_in, const int* in_sizes, int n_in,
                              void* d_out, int out_size)
{
    const float* x    = (const float*)d_in[0];
    const float* Win  = (const float*)d_in[1];
    const float* Wout = (const float*)d_in[2];
    float* out = (float*)d_out;

    int I = in_sizes[0] / NDIM;                 // 32768
    int grid = (I + TILE_I - 1) / TILE_I;       // 147

    cudaFuncSetAttribute(kann_kernel,
                         cudaFuncAttributeMaxDynamicSharedMemorySize, SMEM_BYTES);
    kann_kernel<<<grid, THREADS, SMEM_BYTES>>>(x, Win, Wout, out, I);
}

// round 3
// speedup vs baseline: 1.7191x; 1.7191x over previous
#include <cuda_runtime.h>
#include <math.h>

namespace {
constexpr int NDIM   = 4;
constexpr int KW     = 32;      // N_WIDTH
constexpr int KS     = 33;      // padded k-stride (bank-conflict-free staging)
constexpr int NN     = 193;     // N_NODES
constexpr int TILE_I = 224;
constexpr int THREADS = 1024;
constexpr int IPW    = TILE_I / 32;           // samples per warp = 7

constexpr int WIN_ROWS   = NN * NDIM;         // 772 (node*4+j)
constexpr int WIN_SMEM   = WIN_ROWS * KS;     // 25476 floats
constexpr int WOUT_SMEM  = NN * KS;           // 6369 floats

// shared layout (float words)
constexpr int OFF_WIN   = 0;                               // [(node*4+j)*33 + k]
constexpr int OFF_WOUT  = OFF_WIN + WIN_SMEM;              // [node*33 + k]
constexpr int OFF_PHI_RAW = OFF_WOUT + WOUT_SMEM;          // 31845
constexpr int OFF_PHI   = (OFF_PHI_RAW + 3) & ~3;          // 31848: 16B-aligned for float4
constexpr int OFF_DPHI  = OFF_PHI  + TILE_I * 4 * 4;
constexpr int OFF_DDPHI = OFF_DPHI + TILE_I * 4 * 4;
constexpr int OFF_NODE  = OFF_DDPHI + TILE_I * 4 * 4;      // int [TILE_I*4]
constexpr int SMEM_FLOATS = OFF_NODE + TILE_I * 4;
constexpr int SMEM_BYTES  = SMEM_FLOATS * 4;               // ~174 KB

static_assert((OFF_PHI % 4) == 0, "float4 alignment");
static_assert((OFF_DPHI % 4) == 0, "float4 alignment");
static_assert((OFF_DDPHI % 4) == 0, "float4 alignment");
}

__global__ __launch_bounds__(THREADS, 1)
void kann_kernel(const float* __restrict__ x,
                 const float* __restrict__ Win,
                 const float* __restrict__ Wout,
                 float* __restrict__ out,
                 int I)
{
    extern __shared__ float sm[];
    float*  sWin   = sm + OFF_WIN;
    float*  sWout  = sm + OFF_WOUT;
    float4* sPhi   = (float4*)(sm + OFF_PHI);
    float4* sDphi  = (float4*)(sm + OFF_DPHI);
    float4* sDdphi = (float4*)(sm + OFF_DDPHI);
    int*    sNode  = (int*)(sm + OFF_NODE);

    const int tid    = threadIdx.x;
    const int i_base = blockIdx.x * TILE_I;

    // ---- stage weights into SMEM, transposed so lane==k is contiguous ----
    // consecutive e -> same k, consecutive r -> smem addr stride 33 words
    // -> banks cycle through all 32 -> conflict-free STS.
    for (int e = tid; e < KW * WIN_ROWS; e += THREADS) {
        int k = e / WIN_ROWS;
        int r = e - k * WIN_ROWS;            // node*4 + j
        sWin[r * KS + k] = Win[e];
    }
    for (int e = tid; e < KW * NN; e += THREADS) {
        int k    = e / NN;
        int node = e - k * NN;
        sWout[node * KS + k] = Wout[e];
    }

    const float c0 = -0.5625f, c1 = 1.6875f, c2 = -1.6875f, c3 = 0.5625f;
    const float TH = 1.0f / 3.0f;

    // ---- phase 1: per-(sample,dim) basis values + derivatives ----
    if (tid < TILE_I * NDIM) {
        const int li = tid >> 2;
        const int j  = tid & 3;
        const int i  = i_base + li;
        if (i < I) {
            float xv = x[i * NDIM + j];
            // layer_transform on [-1,1], 193 nodes, 64 elements
            float xs = 192.0f * (xv + 1.0f) / 2.0f;
            float fe = floorf(xs / 3.0f);
            fe = fminf(fmaxf(fe, 0.0f), 63.0f);
            float nl = 3.0f * fe;
            float xr = 2.0f * (xs - nl) / 3.0f - 1.0f;

            float d0 = xr + 1.0f, d1 = xr + TH, d2 = xr - TH, d3 = xr - 1.0f;
            float d01 = d0 * d1, d23 = d2 * d3;
            float d02 = d0 * d2, d03 = d0 * d3, d12 = d1 * d2, d13 = d1 * d3;

            float4 ph, dp, dd;
            ph.x = c0 * (d1 * d23);
            ph.y = c1 * (d0 * d23);
            ph.z = c2 * (d01 * d3);
            ph.w = c3 * (d01 * d2);
            dp.x = c0 * (d23 + d13 + d12);
            dp.y = c1 * (d23 + d03 + d02);
            dp.z = c2 * (d13 + d03 + d01);
            dp.w = c3 * (d12 + d02 + d01);
            float s = d0 + d1 + d2 + d3;
            dd.x = 2.0f * c0 * (s - d0);
            dd.y = 2.0f * c1 * (s - d1);
            dd.z = 2.0f * c2 * (s - d2);
            dd.w = 2.0f * c3 * (s - d3);

            sPhi[tid]   = ph;
            sDphi[tid]  = dp;
            sDdphi[tid] = dd;
            sNode[tid]  = 3 * (int)fe;
        }
    }
    __syncthreads();

    // ---- phase 2: warp = one sample, lane = width k ----
    const int warp = tid >> 5;
    const int lane = tid & 31;
    const int IK   = I * KW;

    #pragma unroll
    for (int s = 0; s < IPW; s++) {
        int li = warp * IPW + s;
        int i  = i_base + li;
        if (i >= I) break;

        float tv = 0.f, dtv = 0.f, ddtv = 0.f;
        #pragma unroll
        for (int j = 0; j < 4; j++) {
            int idx  = li * 4 + j;
            int node = sNode[idx];
            float4 ph = sPhi[idx];
            float4 dp = sDphi[idx];
            float4 dd = sDdphi[idx];
            const float* wb = sWin + (node * 4 + j) * KS + lane;
            float w0 = wb[0 * 4 * KS];
            float w1 = wb[1 * 4 * KS];
            float w2 = wb[2 * 4 * KS];
            float w3 = wb[3 * 4 * KS];
            tv   += w0 * ph.x + w1 * ph.y + w2 * ph.z + w3 * ph.w;
            dtv  += w0 * dp.x + w1 * dp.y + w2 * dp.z + w3 * dp.w;
            ddtv += w0 * dd.x + w1 * dd.y + w2 * dd.z + w3 * dd.w;
        }
        dtv  *= 64.0f;    // 1/delta,   delta = 1/64 exactly
        ddtv *= 4096.0f;  // 1/delta^2

        // outer layer on t, domain [-3,3]
        float xs = 192.0f * (tv + 3.0f) / 6.0f;
        float fe = floorf(xs / 3.0f);
        fe = fminf(fmaxf(fe, 0.0f), 63.0f);
        float nl = 3.0f * fe;
        float xr = 2.0f * (xs - nl) / 3.0f - 1.0f;

        float e0 = xr + 1.0f, e1 = xr + TH, e2 = xr - TH, e3 = xr - 1.0f;
        float e01 = e0 * e1, e23 = e2 * e3;
        float p0 = c0 * (e1 * e23);
        float p1 = c1 * (e0 * e23);
        float p2 = c2 * (e01 * e3);
        float p3 = c3 * (e01 * e2);

        const float* wo = sWout + (3 * (int)fe) * KS + lane;
        float y = p0 * wo[0] + p1 * wo[KS] + p2 * wo[2 * KS] + p3 * wo[3 * KS];

        int o = i * KW + lane;
        out[o]          = y;
        out[o + IK]     = tv;
        out[o + 2 * IK] = dtv;
        out[o + 3 * IK] = ddtv;
    }
}

extern "C" void kernel_launch(void* const* d_in, const int* in_sizes, int n_in,
                              void* d_out, int out_size)
{
    const float* x    = (const float*)d_in[0];
    const float* Win  = (const float*)d_in[1];
    const float* Wout = (const float*)d_in[2];
    float* out = (float*)d_out;

    int I = in_sizes[0] / NDIM;                 // 32768
    int grid = (I + TILE_I - 1) / TILE_I;       // 147

    cudaFuncSetAttribute(kann_kernel,
                         cudaFuncAttributeMaxDynamicSharedMemorySize, SMEM_BYTES);
    kann_kernel<<<grid, THREADS, SMEM_BYTES>>>(x, Win, Wout, out, I);
}